// round 9
// baseline (speedup 1.0000x reference)
#include <cuda_runtime.h>
#include <math.h>

#define B_   32
#define T_   1500
#define E_   512
#define D_   512
#define A_   512
#define H_   4
#define C_   10
#define KK_  201
#define NCH  12
#define TCH  125   // 1500 / 12

// ---------------- scratch (static device arrays; no allocation) ----------------
__device__ float g_dec_a[B_ * H_ * A_];          // [B,H,A]
__device__ float g_conv [B_ * H_ * T_ * C_];     // [B,H,T,C]
__device__ float g_energy[B_ * H_ * T_];         // [B,H,T]
__device__ float g_aw   [B_ * H_ * T_];          // [B,H,T]
__device__ float g_part [B_ * NCH * H_ * E_];    // [B,chunk,H,E]

__device__ __forceinline__ float ftanh(float x) {
    float ax = fabsf(x);
    float t  = __expf(-2.0f * ax);
    float r  = __fdividef(1.0f - t, 1.0f + t);
    return copysignf(r, x);
}

// ---------------- dec_a[b,h,a] = sum_d dec_out[b,d] * w_dec[h,d,a] ----------------
__global__ __launch_bounds__(256) void dec_proj_kernel(
    const float* __restrict__ dec_out, const float* __restrict__ w_dec)
{
    int b = blockIdx.x, h = blockIdx.y, tid = threadIdx.x;
    __shared__ float s_dec[D_];
    for (int i = tid; i < D_; i += 256) s_dec[i] = dec_out[b * D_ + i];
    __syncthreads();
    for (int a = tid; a < A_; a += 256) {
        float acc = 0.f;
        const float* w = w_dec + (size_t)(h * D_) * A_ + a;
        #pragma unroll 8
        for (int d = 0; d < D_; d++) acc = fmaf(s_dec[d], w[(size_t)d * A_], acc);
        g_dec_a[(b * H_ + h) * A_ + a] = acc;
    }
}

// ---------------- grouped conv: g_conv[b,h,t,c] ----------------
__global__ __launch_bounds__(256) void conv_kernel(
    const float* __restrict__ aw_step, const float* __restrict__ conv_k)
{
    int b = blockIdx.x, h = blockIdx.y, tid = threadIdx.x;
    __shared__ float s_aw[T_];
    __shared__ float s_k[C_][KK_];
    for (int i = tid; i < T_; i += 256) s_aw[i] = aw_step[(i * H_) + h + (size_t)b * T_ * H_];
    for (int i = tid; i < C_ * KK_; i += 256) s_k[i / KK_][i % KK_] = conv_k[(size_t)(h * C_) * KK_ + i];
    __syncthreads();
    for (int t = tid; t < T_; t += 256) {
        int klo = max(0, 100 - t);
        int khi = min(KK_, T_ + 100 - t);
        float acc[C_];
        #pragma unroll
        for (int c = 0; c < C_; c++) acc[c] = 0.f;
        for (int k = klo; k < khi; k++) {
            float x = s_aw[t + k - 100];
            #pragma unroll
            for (int c = 0; c < C_; c++) acc[c] = fmaf(x, s_k[c][k], acc[c]);
        }
        #pragma unroll
        for (int c = 0; c < C_; c++)
            g_conv[((size_t)(b * H_ + h) * T_ + t) * C_ + c] = acc[c];
    }
}

// ---------------- fused energy kernel ----------------
// block = (t_tile of 64, h, b); loops all 8 a-tiles internally; 64x64 GEMM tiles,
// epilogue: + bias + dec_a + conv@w_conv, tanh, *v, reduce over A -> energy[b,h,t]
__global__ __launch_bounds__(256, 3) void energy_kernel(
    const float* __restrict__ enc, const float* __restrict__ w_enc,
    const float* __restrict__ b_enc, const float* __restrict__ w_conv,
    const float* __restrict__ v)
{
    int tile = blockIdx.x, h = blockIdx.y, b = blockIdx.z;
    int t0 = tile * 64;
    int tid = threadIdx.x;
    int tx = tid & 15, ty = tid >> 4;

    __shared__ float As[64][33];      // [t][k]
    __shared__ float Bs[32][64];      // [k][a]
    __shared__ float s_cl[64][C_];    // conv features per t
    __shared__ float s_bias[64];
    __shared__ float s_wv[C_][64];
    __shared__ float s_vv[64];
    __shared__ float s_red[64][17];

    for (int i = tid; i < 64 * C_; i += 256) {
        int r = i / C_, c = i % C_;
        int t = t0 + r;
        s_cl[r][c] = (t < T_) ? g_conv[((size_t)(b * H_ + h) * T_ + t) * C_ + c] : 0.f;
    }

    float ep[4] = {0.f, 0.f, 0.f, 0.f};

    for (int at = 0; at < 8; at++) {
        int a0 = at * 64;
        __syncthreads();  // previous epilogue done reading s_bias/s_wv/s_vv
        if (tid < 64) {
            s_bias[tid] = b_enc[h * A_ + a0 + tid] + g_dec_a[(b * H_ + h) * A_ + a0 + tid];
            s_vv[tid]   = v[h * A_ + a0 + tid];
        }
        for (int i = tid; i < C_ * 64; i += 256) {
            int c = i >> 6, aa = i & 63;
            s_wv[c][aa] = w_conv[(size_t)(h * C_ + c) * A_ + a0 + aa];
        }

        float acc[4][4] = {};
        for (int kc = 0; kc < 16; kc++) {
            __syncthreads();
            {   // load As: enc[b, t0..t0+63, kc*32..+31]
                int col = tid & 31, row0 = tid >> 5;
                int k = kc * 32 + col;
                #pragma unroll
                for (int p = 0; p < 8; p++) {
                    int r = row0 + p * 8;
                    int t = t0 + r;
                    As[r][col] = (t < T_) ? enc[(size_t)(b * T_ + t) * E_ + k] : 0.f;
                }
            }
            {   // load Bs: w_enc[h, kc*32..+31, a0..a0+63]
                #pragma unroll
                for (int p = 0; p < 8; p++) {
                    int idx = p * 256 + tid;
                    int r = idx >> 6, cc = idx & 63;
                    Bs[r][cc] = w_enc[((size_t)(h * E_) + kc * 32 + r) * A_ + a0 + cc];
                }
            }
            __syncthreads();
            #pragma unroll
            for (int kk = 0; kk < 32; kk++) {
                float4 bq = *(const float4*)&Bs[kk][tx * 4];
                float a0v = As[ty * 4 + 0][kk];
                float a1v = As[ty * 4 + 1][kk];
                float a2v = As[ty * 4 + 2][kk];
                float a3v = As[ty * 4 + 3][kk];
                acc[0][0] = fmaf(a0v, bq.x, acc[0][0]); acc[0][1] = fmaf(a0v, bq.y, acc[0][1]);
                acc[0][2] = fmaf(a0v, bq.z, acc[0][2]); acc[0][3] = fmaf(a0v, bq.w, acc[0][3]);
                acc[1][0] = fmaf(a1v, bq.x, acc[1][0]); acc[1][1] = fmaf(a1v, bq.y, acc[1][1]);
                acc[1][2] = fmaf(a1v, bq.z, acc[1][2]); acc[1][3] = fmaf(a1v, bq.w, acc[1][3]);
                acc[2][0] = fmaf(a2v, bq.x, acc[2][0]); acc[2][1] = fmaf(a2v, bq.y, acc[2][1]);
                acc[2][2] = fmaf(a2v, bq.z, acc[2][2]); acc[2][3] = fmaf(a2v, bq.w, acc[2][3]);
                acc[3][0] = fmaf(a3v, bq.x, acc[3][0]); acc[3][1] = fmaf(a3v, bq.y, acc[3][1]);
                acc[3][2] = fmaf(a3v, bq.z, acc[3][2]); acc[3][3] = fmaf(a3v, bq.w, acc[3][3]);
            }
        }
        // epilogue for this a-tile
        float4 bqb = *(const float4*)&s_bias[tx * 4];
        float4 vq  = *(const float4*)&s_vv[tx * 4];
        #pragma unroll
        for (int i = 0; i < 4; i++) {
            float cw0 = 0.f, cw1 = 0.f, cw2 = 0.f, cw3 = 0.f;
            #pragma unroll
            for (int c = 0; c < C_; c++) {
                float clv = s_cl[ty * 4 + i][c];
                float4 wq = *(const float4*)&s_wv[c][tx * 4];
                cw0 = fmaf(clv, wq.x, cw0); cw1 = fmaf(clv, wq.y, cw1);
                cw2 = fmaf(clv, wq.z, cw2); cw3 = fmaf(clv, wq.w, cw3);
            }
            float e = 0.f;
            e = fmaf(ftanh(acc[i][0] + bqb.x + cw0), vq.x, e);
            e = fmaf(ftanh(acc[i][1] + bqb.y + cw1), vq.y, e);
            e = fmaf(ftanh(acc[i][2] + bqb.z + cw2), vq.z, e);
            e = fmaf(ftanh(acc[i][3] + bqb.w + cw3), vq.w, e);
            ep[i] += e;
        }
    }

    __syncthreads();
    #pragma unroll
    for (int i = 0; i < 4; i++) s_red[ty * 4 + i][tx] = ep[i];
    __syncthreads();
    if (tid < 64) {
        float s = 0.f;
        #pragma unroll
        for (int x = 0; x < 16; x++) s += s_red[tid][x];
        int t = t0 + tid;
        if (t < T_) g_energy[(b * H_ + h) * T_ + t] = s;
    }
}

// ---------------- masked softmax over T per (b,h); writes aw to d_out + scratch ----------------
__global__ __launch_bounds__(256) void softmax_kernel(
    const int* __restrict__ x_lens, float* __restrict__ aw_out)
{
    int b = blockIdx.x, h = blockIdx.y, tid = threadIdx.x;
    __shared__ float s_em[T_];
    __shared__ float s_red[256];
    int len = x_lens[b];
    const float* e = g_energy + (size_t)(b * H_ + h) * T_;

    float mx = -3.4e38f;
    for (int t = tid; t < T_; t += 256) {
        float m = (t < len) ? 1.0f : -1024.0f;
        float val = e[t] * m;   // SHARPENING = 1.0
        s_em[t] = val;
        mx = fmaxf(mx, val);
    }
    s_red[tid] = mx; __syncthreads();
    for (int s = 128; s > 0; s >>= 1) { if (tid < s) s_red[tid] = fmaxf(s_red[tid], s_red[tid + s]); __syncthreads(); }
    mx = s_red[0];
    __syncthreads();
    float sum = 0.f;
    for (int t = tid; t < T_; t += 256) { float ex = __expf(s_em[t] - mx); s_em[t] = ex; sum += ex; }
    s_red[tid] = sum; __syncthreads();
    for (int s = 128; s > 0; s >>= 1) { if (tid < s) s_red[tid] += s_red[tid + s]; __syncthreads(); }
    float inv = 1.0f / s_red[0];
    for (int t = tid; t < T_; t += 256) {
        float a = s_em[t] * inv;
        g_aw[(size_t)(b * H_ + h) * T_ + t] = a;
        aw_out[(size_t)(b * T_ + t) * H_ + h] = a;
    }
}

// ---------------- ctx partials: g_part[b,chunk,h,e] = sum_{t in chunk} enc[b,t,e]*aw[b,h,t] ----------------
__global__ __launch_bounds__(256) void ctx_partial_kernel(const float* __restrict__ enc)
{
    int chunk = blockIdx.x, b = blockIdx.y, tid = threadIdx.x;
    int t0 = chunk * TCH;
    __shared__ float s_aw[H_][TCH];
    for (int i = tid; i < H_ * TCH; i += 256) {
        int h = i / TCH, tt = i % TCH;
        s_aw[h][tt] = g_aw[(size_t)(b * H_ + h) * T_ + t0 + tt];
    }
    __syncthreads();
    float acc0[H_] = {}, acc1[H_] = {};
    int e0 = tid, e1 = tid + 256;
    const float* ep = enc + (size_t)(b * T_ + t0) * E_;
    #pragma unroll 4
    for (int tt = 0; tt < TCH; tt++) {
        float f0 = ep[(size_t)tt * E_ + e0];
        float f1 = ep[(size_t)tt * E_ + e1];
        #pragma unroll
        for (int h = 0; h < H_; h++) {
            float a = s_aw[h][tt];
            acc0[h] = fmaf(f0, a, acc0[h]);
            acc1[h] = fmaf(f1, a, acc1[h]);
        }
    }
    float* p = g_part + (size_t)((b * NCH + chunk) * H_) * E_;
    #pragma unroll
    for (int h = 0; h < H_; h++) { p[h * E_ + e0] = acc0[h]; p[h * E_ + e1] = acc1[h]; }
}

// ---------------- reduce partials + MHA projection -> ctx out [B,E] ----------------
__global__ __launch_bounds__(256) void final_kernel(
    const float* __restrict__ w_mha, const float* __restrict__ b_mha, float* __restrict__ out)
{
    int b = blockIdx.x, tid = threadIdx.x;
    __shared__ float s_ctx[H_ * E_];
    for (int i = tid; i < H_ * E_; i += 256) {
        float s = 0.f;
        #pragma unroll
        for (int ch = 0; ch < NCH; ch++)
            s += g_part[(size_t)((b * NCH + ch) * H_) * E_ + i];
        s_ctx[i] = s;
    }
    __syncthreads();
    int ea = tid, eb = tid + 256;
    float acc_a = b_mha[ea], acc_b = b_mha[eb];
    #pragma unroll 8
    for (int he = 0; he < H_ * E_; he++) {
        float c = s_ctx[he];
        const float* w = w_mha + (size_t)he * E_;
        acc_a = fmaf(c, w[ea], acc_a);
        acc_b = fmaf(c, w[eb], acc_b);
    }
    out[b * E_ + ea] = acc_a;
    out[b * E_ + eb] = acc_b;
}

// ---------------- launch ----------------
extern "C" void kernel_launch(void* const* d_in, const int* in_sizes, int n_in,
                              void* d_out, int out_size)
{
    const float* enc     = (const float*)d_in[0];
    const int*   x_lens  = (const int*)  d_in[1];
    const float* dec_out = (const float*)d_in[2];
    const float* aw_step = (const float*)d_in[3];
    const float* w_enc   = (const float*)d_in[4];
    const float* b_enc   = (const float*)d_in[5];
    const float* w_dec   = (const float*)d_in[6];
    const float* w_conv  = (const float*)d_in[7];
    const float* conv_k  = (const float*)d_in[8];
    const float* v       = (const float*)d_in[9];
    const float* w_mha   = (const float*)d_in[10];
    const float* b_mha   = (const float*)d_in[11];

    float* out     = (float*)d_out;
    float* ctx_out = out;              // B*E floats
    float* aw_out  = out + B_ * E_;    // B*T*H floats

    dec_proj_kernel<<<dim3(B_, H_), 256>>>(dec_out, w_dec);
    conv_kernel<<<dim3(B_, H_), 256>>>(aw_step, conv_k);
    energy_kernel<<<dim3((T_ + 63) / 64, H_, B_), 256>>>(enc, w_enc, b_enc, w_conv, v);
    softmax_kernel<<<dim3(B_, H_), 256>>>(x_lens, aw_out);
    ctx_partial_kernel<<<dim3(NCH, B_), 256>>>(enc);
    final_kernel<<<B_, 256>>>(w_mha, b_mha, ctx_out);
}

// round 12
// speedup vs baseline: 2.2200x; 2.2200x over previous
#include <cuda_runtime.h>
#include <cuda_bf16.h>
#include <math.h>

#define B_   32
#define T_   1500
#define E_   512
#define D_   512
#define A_   512
#define H_   4
#define C_   10
#define KK_  201
#define NCH  12
#define TCH  125   // 1500 / 12

#define KTOT 528   // padded K: 512 enc + 10 conv + 6 zero

// ---------------- scratch (static device arrays; no allocation) ----------------
__device__ float g_dec_a[B_ * H_ * A_];          // [B,H,A]
__device__ float g_energy[B_ * H_ * T_];         // [B,H,T]
__device__ float g_aw   [B_ * H_ * T_];          // [B,H,T]
__device__ float g_part [B_ * NCH * H_ * E_];    // [B,chunk,H,E]
__device__ __align__(16) __nv_bfloat16 g_enc_hi[B_ * T_ * E_];   // 49 MB
__device__ __align__(16) __nv_bfloat16 g_enc_lo[B_ * T_ * E_];
__device__ __align__(16) __nv_bfloat16 g_wall_hi[H_ * A_ * KTOT]; // [h][a][k]
__device__ __align__(16) __nv_bfloat16 g_wall_lo[H_ * A_ * KTOT];
__device__ __align__(16) __nv_bfloat16 g_convh[B_ * H_ * T_ * 16]; // conv feats, 16-padded
__device__ __align__(16) __nv_bfloat16 g_convl[B_ * H_ * T_ * 16];

__device__ __forceinline__ float ftanh(float x) {
    float ax = fabsf(x);
    float t  = __expf(-2.0f * ax);
    float r  = __fdividef(1.0f - t, 1.0f + t);
    return copysignf(r, x);
}

// ======================= PTX helpers (base-target only) =======================
__device__ __forceinline__ unsigned smem_u32(const void* p) {
    unsigned a;
    asm("{ .reg .u64 t; cvta.to.shared.u64 t, %1; cvt.u32.u64 %0, t; }" : "=r"(a) : "l"(p));
    return a;
}
__device__ __forceinline__ void cp16(unsigned dst, const void* src, int sz) {
    asm volatile("cp.async.cg.shared.global [%0], [%1], 16, %2;"
                 :: "r"(dst), "l"(__cvta_generic_to_global(src)), "r"(sz));
}
__device__ __forceinline__ void cp_commit() {
    asm volatile("cp.async.commit_group;" ::: "memory");
}
__device__ __forceinline__ void cp_wait1() {
    asm volatile("cp.async.wait_group 1;" ::: "memory");
}
__device__ __forceinline__ void cp_wait0() {
    asm volatile("cp.async.wait_group 0;" ::: "memory");
}
__device__ __forceinline__ void ldsm4(unsigned* r, unsigned addr) {
    asm volatile("ldmatrix.sync.aligned.m8n8.x4.shared.b16 {%0,%1,%2,%3}, [%4];"
                 : "=r"(r[0]), "=r"(r[1]), "=r"(r[2]), "=r"(r[3]) : "r"(addr));
}
__device__ __forceinline__ void mma16816(float* c, const unsigned* a, unsigned b0, unsigned b1) {
    asm volatile("mma.sync.aligned.m16n8k16.row.col.f32.bf16.bf16.f32 "
                 "{%0,%1,%2,%3}, {%4,%5,%6,%7}, {%8,%9}, {%0,%1,%2,%3};"
                 : "+f"(c[0]), "+f"(c[1]), "+f"(c[2]), "+f"(c[3])
                 : "r"(a[0]), "r"(a[1]), "r"(a[2]), "r"(a[3]), "r"(b0), "r"(b1));
}

// ---------------- prep: split enc into bf16 hi/lo ----------------
__global__ __launch_bounds__(256) void prep_enc_kernel(const float* __restrict__ enc)
{
    size_t i = ((size_t)blockIdx.x * 256 + threadIdx.x) * 4;
    if (i >= (size_t)B_ * T_ * E_) return;
    float4 x = *(const float4*)(enc + i);
    __nv_bfloat16 h0 = __float2bfloat16(x.x), h1 = __float2bfloat16(x.y),
                  h2 = __float2bfloat16(x.z), h3 = __float2bfloat16(x.w);
    __nv_bfloat16 l0 = __float2bfloat16(x.x - __bfloat162float(h0));
    __nv_bfloat16 l1 = __float2bfloat16(x.y - __bfloat162float(h1));
    __nv_bfloat16 l2 = __float2bfloat16(x.z - __bfloat162float(h2));
    __nv_bfloat16 l3 = __float2bfloat16(x.w - __bfloat162float(h3));
    uint2 hv = make_uint2((unsigned)__bfloat16_as_ushort(h0) | ((unsigned)__bfloat16_as_ushort(h1) << 16),
                          (unsigned)__bfloat16_as_ushort(h2) | ((unsigned)__bfloat16_as_ushort(h3) << 16));
    uint2 lv = make_uint2((unsigned)__bfloat16_as_ushort(l0) | ((unsigned)__bfloat16_as_ushort(l1) << 16),
                          (unsigned)__bfloat16_as_ushort(l2) | ((unsigned)__bfloat16_as_ushort(l3) << 16));
    *(uint2*)(g_enc_hi + i) = hv;
    *(uint2*)(g_enc_lo + i) = lv;
}

// ---------------- prep: w_all[h][a][k] = concat(w_enc^T, w_conv^T, 0) hi/lo ----------------
__global__ __launch_bounds__(256) void prep_w_kernel(
    const float* __restrict__ w_enc, const float* __restrict__ w_conv)
{
    int idx = blockIdx.x * 256 + threadIdx.x;
    if (idx >= H_ * A_ * KTOT) return;
    int k  = idx % KTOT;
    int ha = idx / KTOT;
    int a  = ha % A_;
    int hh = ha / A_;
    float val = 0.f;
    if (k < 512)      val = w_enc[((size_t)hh * 512 + k) * 512 + a];
    else if (k < 522) val = w_conv[((size_t)hh * C_ + (k - 512)) * 512 + a];
    __nv_bfloat16 hi = __float2bfloat16(val);
    float lo = val - __bfloat162float(hi);
    g_wall_hi[idx] = hi;
    g_wall_lo[idx] = __float2bfloat16(lo);
}

// ---------------- dec_a[b,h,a] = sum_d dec_out[b,d] * w_dec[h,d,a] ----------------
__global__ __launch_bounds__(256) void dec_proj_kernel(
    const float* __restrict__ dec_out, const float* __restrict__ w_dec)
{
    int b = blockIdx.x, h = blockIdx.y, tid = threadIdx.x;
    __shared__ float s_dec[D_];
    for (int i = tid; i < D_; i += 256) s_dec[i] = dec_out[b * D_ + i];
    __syncthreads();
    for (int a = tid; a < A_; a += 256) {
        float acc = 0.f;
        const float* w = w_dec + (size_t)(h * D_) * A_ + a;
        #pragma unroll 8
        for (int d = 0; d < D_; d++) acc = fmaf(s_dec[d], w[(size_t)d * A_], acc);
        g_dec_a[(b * H_ + h) * A_ + a] = acc;
    }
}

// ---------------- grouped conv -> bf16 hi/lo features [B,H,T,16] ----------------
__global__ __launch_bounds__(256) void conv_kernel(
    const float* __restrict__ aw_step, const float* __restrict__ conv_k)
{
    int b = blockIdx.x, h = blockIdx.y, tid = threadIdx.x;
    __shared__ float s_aw[T_];
    __shared__ float s_k[C_][KK_];
    for (int i = tid; i < T_; i += 256) s_aw[i] = aw_step[(i * H_) + h + (size_t)b * T_ * H_];
    for (int i = tid; i < C_ * KK_; i += 256) s_k[i / KK_][i % KK_] = conv_k[(size_t)(h * C_) * KK_ + i];
    __syncthreads();
    for (int t = tid; t < T_; t += 256) {
        int klo = max(0, 100 - t);
        int khi = min(KK_, T_ + 100 - t);
        float acc[C_];
        #pragma unroll
        for (int c = 0; c < C_; c++) acc[c] = 0.f;
        for (int k = klo; k < khi; k++) {
            float x = s_aw[t + k - 100];
            #pragma unroll
            for (int c = 0; c < C_; c++) acc[c] = fmaf(x, s_k[c][k], acc[c]);
        }
        size_t base = ((size_t)(b * H_ + h) * T_ + t) * 16;
        #pragma unroll
        for (int c = 0; c < 16; c++) {
            float val = (c < C_) ? acc[c] : 0.f;
            __nv_bfloat16 hi = __float2bfloat16(val);
            float lo = val - __bfloat162float(hi);
            g_convh[base + c] = hi;
            g_convl[base + c] = __float2bfloat16(lo);
        }
    }
}

// ======================= fused HMMA energy kernel =======================
// grid (12, H, B), 256 threads (8 warps). CTA: 128 t rows x 512 a (4 tiles of 128).
// K = 528 per a-tile: 8 chunks of 64 (enc) + 1 chunk of 16 (conv).
// Split bf16: D = Ah*Bh + Ah*Bl + Al*Bh (fp32 accum).
// Double-buffered cp.async staging overlapped with mma.
// Epilogue per a-tile: energy += sum_a tanh(D + bias)*v.

#define TSTRIDE 72          // padded smem row stride (bf16 elems) -> 144 B, ldmatrix conflict-free
#define TILE_B  (128 * TSTRIDE * 2)   // 18432 bytes per tile
#define BUF_B   (4 * TILE_B)          // Ah, Al, Bh, Bl = 73728
#define SMEM_E  (2 * BUF_B)           // 147456

__global__ __launch_bounds__(256) void energy_mma_kernel(
    const float* __restrict__ b_enc, const float* __restrict__ v)
{
    extern __shared__ char dynsmem[];
    __shared__ float s_bias[A_];
    __shared__ float s_vv[A_];
    __shared__ float s_e[128];

    int tile = blockIdx.x, h = blockIdx.y, b = blockIdx.z;
    int t0 = tile * 128;
    int tid = threadIdx.x;
    int wid = tid >> 5, lane = tid & 31;
    int wt = wid & 3, wa = wid >> 2;          // warp grid 4(t) x 2(a)

    unsigned sb = smem_u32(dynsmem);

    for (int i = tid; i < A_; i += 256) {
        s_bias[i] = b_enc[h * A_ + i] + g_dec_a[(b * H_ + h) * A_ + i];
        s_vv[i]   = v[h * A_ + i];
    }
    if (tid < 128) s_e[tid] = 0.f;

    // ---- staging lambda-ish macro via function scope ----
    // chunk g: at = g/9, c = g%9; buffer g&1
    auto stage = [&](int g) {
        int at = g / 9, c = g % 9;
        unsigned base = sb + (unsigned)(g & 1) * BUF_B;
        if (c < 8) {
            // A: enc hi/lo [128 rows][64 k]
            for (int s = tid; s < 2048; s += 256) {
                int half = s >> 10;
                int r = (s >> 3) & 127;
                int seg = s & 7;
                int t = t0 + r;
                int tc = t < T_ ? t : T_ - 1;
                const __nv_bfloat16* src = (half ? g_enc_lo : g_enc_hi)
                    + ((size_t)(b * T_ + tc) * E_ + c * 64 + seg * 8);
                cp16(base + half * TILE_B + r * 144 + seg * 16, src, (t < T_) ? 16 : 0);
            }
            // B: w_all hi/lo [128 a rows][64 k]
            for (int s = tid; s < 2048; s += 256) {
                int half = s >> 10;
                int r = (s >> 3) & 127;
                int seg = s & 7;
                const __nv_bfloat16* src = (half ? g_wall_lo : g_wall_hi)
                    + ((size_t)(h * A_ + at * 128 + r) * KTOT + c * 64 + seg * 8);
                cp16(base + 2 * TILE_B + half * TILE_B + r * 144 + seg * 16, src, 16);
            }
        } else {
            // conv chunk: 16 wide
            for (int s = tid; s < 512; s += 256) {
                int half = s >> 8;
                int r = (s >> 1) & 127;
                int seg = s & 1;
                int t = t0 + r;
                int tc = t < T_ ? t : T_ - 1;
                const __nv_bfloat16* src = (half ? g_convl : g_convh)
                    + ((size_t)((b * H_ + h) * T_ + tc) * 16 + seg * 8);
                cp16(base + half * TILE_B + r * 144 + seg * 16, src, (t < T_) ? 16 : 0);
            }
            for (int s = tid; s < 512; s += 256) {
                int half = s >> 8;
                int r = (s >> 1) & 127;
                int seg = s & 1;
                const __nv_bfloat16* src = (half ? g_wall_lo : g_wall_hi)
                    + ((size_t)(h * A_ + at * 128 + r) * KTOT + 512 + seg * 8);
                cp16(base + 2 * TILE_B + half * TILE_B + r * 144 + seg * 16, src, 16);
            }
        }
        cp_commit();
    };

    // lane-dependent ldmatrix byte offsets (within a tile)
    // A (m16k16): row = mbase + (lane&15), col8 = (lane>>4)*8
    unsigned aoff0 = (unsigned)((wt * 32 + 0  + (lane & 15)) * 144 + ((lane >> 4) << 4));
    unsigned aoff1 = (unsigned)((wt * 32 + 16 + (lane & 15)) * 144 + ((lane >> 4) << 4));
    // B (n16k16 pair): row = nbase + (lane&7) + ((lane>>4)<<3), col8 = ((lane>>3)&1)*8
    unsigned brow = (unsigned)((lane & 7) + ((lane >> 4) << 3));
    unsigned bcol = (unsigned)(((lane >> 3) & 1) << 4);

    float acc[2][8][4];

    stage(0);
    __syncthreads();   // also covers s_bias/s_e init

    for (int g = 0; g < 36; g++) {
        int at = g / 9, c = g % 9;
        if (g + 1 < 36) stage(g + 1);
        if (g + 1 < 36) cp_wait1(); else cp_wait0();
        __syncthreads();

        if (c == 0) {
            #pragma unroll
            for (int mi = 0; mi < 2; mi++)
                #pragma unroll
                for (int nn = 0; nn < 8; nn++)
                    #pragma unroll
                    for (int q = 0; q < 4; q++) acc[mi][nn][q] = 0.f;
        }

        unsigned base = sb + (unsigned)(g & 1) * BUF_B;
        unsigned sAh = base, sAl = base + TILE_B;
        unsigned sBh = base + 2 * TILE_B, sBl = base + 3 * TILE_B;
        int nks = (c < 8) ? 4 : 1;

        for (int ks = 0; ks < nks; ks++) {
            unsigned kb = (unsigned)(ks << 5);   // ks*16 elems * 2B
            unsigned ah[2][4], al[2][4], bh[4][4], bl[4][4];
            ldsm4(ah[0], sAh + aoff0 + kb);
            ldsm4(ah[1], sAh + aoff1 + kb);
            ldsm4(al[0], sAl + aoff0 + kb);
            ldsm4(al[1], sAl + aoff1 + kb);
            #pragma unroll
            for (int np = 0; np < 4; np++) {
                unsigned off = (unsigned)((wa * 64 + np * 16 + brow) * 144) + bcol + kb;
                ldsm4(bh[np], sBh + off);
                ldsm4(bl[np], sBl + off);
            }
            #pragma unroll
            for (int mi = 0; mi < 2; mi++) {
                #pragma unroll
                for (int np = 0; np < 4; np++) {
                    #pragma unroll
                    for (int sub = 0; sub < 2; sub++) {
                        int nn = np * 2 + sub;
                        mma16816(acc[mi][nn], ah[mi], bh[np][sub * 2], bh[np][sub * 2 + 1]);
                        mma16816(acc[mi][nn], ah[mi], bl[np][sub * 2], bl[np][sub * 2 + 1]);
                        mma16816(acc[mi][nn], al[mi], bh[np][sub * 2], bh[np][sub * 2 + 1]);
                    }
                }
            }
        }

        if (c == 8) {
            // epilogue for a-tile `at`
            #pragma unroll
            for (int mi = 0; mi < 2; mi++) {
                float e0 = 0.f, e1 = 0.f;
                #pragma unroll
                for (int nn = 0; nn < 8; nn++) {
                    int ng = at * 128 + wa * 64 + nn * 8 + (lane & 3) * 2;
                    float b0v = s_bias[ng], b1v = s_bias[ng + 1];
                    float v0  = s_vv[ng],  v1  = s_vv[ng + 1];
                    e0 = fmaf(ftanh(acc[mi][nn][0] + b0v), v0, e0);
                    e0 = fmaf(ftanh(acc[mi][nn][1] + b1v), v1, e0);
                    e1 = fmaf(ftanh(acc[mi][nn][2] + b0v), v0, e1);
                    e1 = fmaf(ftanh(acc[mi][nn][3] + b1v), v1, e1);
                }
                e0 += __shfl_xor_sync(0xFFFFFFFF, e0, 1);
                e0 += __shfl_xor_sync(0xFFFFFFFF, e0, 2);
                e1 += __shfl_xor_sync(0xFFFFFFFF, e1, 1);
                e1 += __shfl_xor_sync(0xFFFFFFFF, e1, 2);
                if ((lane & 3) == 0) {
                    int r = wt * 32 + mi * 16 + (lane >> 2);
                    atomicAdd(&s_e[r], e0);
                    atomicAdd(&s_e[r + 8], e1);
                }
            }
        }
        __syncthreads();
    }

    if (tid < 128) {
        int t = t0 + tid;
        if (t < T_) g_energy[(b * H_ + h) * T_ + t] = s_e[tid];
    }
}

// ---------------- masked softmax over T per (b,h) ----------------
__global__ __launch_bounds__(256) void softmax_kernel(
    const int* __restrict__ x_lens, float* __restrict__ aw_out)
{
    int b = blockIdx.x, h = blockIdx.y, tid = threadIdx.x;
    __shared__ float s_em[T_];
    __shared__ float s_red[256];
    int len = x_lens[b];
    const float* e = g_energy + (size_t)(b * H_ + h) * T_;

    float mx = -3.4e38f;
    for (int t = tid; t < T_; t += 256) {
        float m = (t < len) ? 1.0f : -1024.0f;
        float val = e[t] * m;
        s_em[t] = val;
        mx = fmaxf(mx, val);
    }
    s_red[tid] = mx; __syncthreads();
    for (int s = 128; s > 0; s >>= 1) { if (tid < s) s_red[tid] = fmaxf(s_red[tid], s_red[tid + s]); __syncthreads(); }
    mx = s_red[0];
    __syncthreads();
    float sum = 0.f;
    for (int t = tid; t < T_; t += 256) { float ex = __expf(s_em[t] - mx); s_em[t] = ex; sum += ex; }
    s_red[tid] = sum; __syncthreads();
    for (int s = 128; s > 0; s >>= 1) { if (tid < s) s_red[tid] += s_red[tid + s]; __syncthreads(); }
    float inv = 1.0f / s_red[0];
    for (int t = tid; t < T_; t += 256) {
        float a = s_em[t] * inv;
        g_aw[(size_t)(b * H_ + h) * T_ + t] = a;
        aw_out[(size_t)(b * T_ + t) * H_ + h] = a;
    }
}

// ---------------- ctx partials ----------------
__global__ __launch_bounds__(256) void ctx_partial_kernel(const float* __restrict__ enc)
{
    int chunk = blockIdx.x, b = blockIdx.y, tid = threadIdx.x;
    int t0 = chunk * TCH;
    __shared__ float s_aw[H_][TCH];
    for (int i = tid; i < H_ * TCH; i += 256) {
        int h = i / TCH, tt = i % TCH;
        s_aw[h][tt] = g_aw[(size_t)(b * H_ + h) * T_ + t0 + tt];
    }
    __syncthreads();
    float acc0[H_] = {}, acc1[H_] = {};
    int e0 = tid, e1 = tid + 256;
    const float* ep = enc + (size_t)(b * T_ + t0) * E_;
    #pragma unroll 4
    for (int tt = 0; tt < TCH; tt++) {
        float f0 = ep[(size_t)tt * E_ + e0];
        float f1 = ep[(size_t)tt * E_ + e1];
        #pragma unroll
        for (int h = 0; h < H_; h++) {
            float a = s_aw[h][tt];
            acc0[h] = fmaf(f0, a, acc0[h]);
            acc1[h] = fmaf(f1, a, acc1[h]);
        }
    }
    float* p = g_part + (size_t)((b * NCH + chunk) * H_) * E_;
    #pragma unroll
    for (int h = 0; h < H_; h++) { p[h * E_ + e0] = acc0[h]; p[h * E_ + e1] = acc1[h]; }
}

// ---------------- reduce partials + MHA projection ----------------
__global__ __launch_bounds__(256) void final_kernel(
    const float* __restrict__ w_mha, const float* __restrict__ b_mha, float* __restrict__ out)
{
    int b = blockIdx.x, tid = threadIdx.x;
    __shared__ float s_ctx[H_ * E_];
    for (int i = tid; i < H_ * E_; i += 256) {
        float s = 0.f;
        #pragma unroll
        for (int ch = 0; ch < NCH; ch++)
            s += g_part[(size_t)((b * NCH + ch) * H_) * E_ + i];
        s_ctx[i] = s;
    }
    __syncthreads();
    int ea = tid, eb = tid + 256;
    float acc_a = b_mha[ea], acc_b = b_mha[eb];
    #pragma unroll 8
    for (int he = 0; he < H_ * E_; he++) {
        float c = s_ctx[he];
        const float* w = w_mha + (size_t)he * E_;
        acc_a = fmaf(c, w[ea], acc_a);
        acc_b = fmaf(c, w[eb], acc_b);
    }
    out[b * E_ + ea] = acc_a;
    out[b * E_ + eb] = acc_b;
}

// ---------------- launch ----------------
extern "C" void kernel_launch(void* const* d_in, const int* in_sizes, int n_in,
                              void* d_out, int out_size)
{
    const float* enc     = (const float*)d_in[0];
    const int*   x_lens  = (const int*)  d_in[1];
    const float* dec_out = (const float*)d_in[2];
    const float* aw_step = (const float*)d_in[3];
    const float* w_enc   = (const float*)d_in[4];
    const float* b_enc   = (const float*)d_in[5];
    const float* w_dec   = (const float*)d_in[6];
    const float* w_conv  = (const float*)d_in[7];
    const float* conv_k  = (const float*)d_in[8];
    const float* v       = (const float*)d_in[9];
    const float* w_mha   = (const float*)d_in[10];
    const float* b_mha   = (const float*)d_in[11];

    float* out     = (float*)d_out;
    float* ctx_out = out;              // B*E floats
    float* aw_out  = out + B_ * E_;    // B*T*H floats

    cudaFuncSetAttribute(energy_mma_kernel, cudaFuncAttributeMaxDynamicSharedMemorySize, SMEM_E);

    prep_enc_kernel<<<(B_ * T_ * E_ / 4 + 255) / 256, 256>>>(enc);
    prep_w_kernel<<<(H_ * A_ * KTOT + 255) / 256, 256>>>(w_enc, w_conv);
    dec_proj_kernel<<<dim3(B_, H_), 256>>>(dec_out, w_dec);
    conv_kernel<<<dim3(B_, H_), 256>>>(aw_step, conv_k);
    energy_mma_kernel<<<dim3(NCH, H_, B_), 256, SMEM_E>>>(b_enc, v);
    softmax_kernel<<<dim3(B_, H_), 256>>>(x_lens, aw_out);
    ctx_partial_kernel<<<dim3(NCH, B_), 256>>>(enc);
    final_kernel<<<B_, 256>>>(w_mha, b_mha, ctx_out);
}